// round 1
// baseline (speedup 1.0000x reference)
#include <cuda_runtime.h>
#include <cuda_bf16.h>

#define NN 50000
#define NE 1600000
#define EP 1650000     // NE + NN self loops
#define FW 128         // H*C feature width

// ---------------- scratch (device globals; no allocation allowed) ------------
__device__ float    g_xl[(size_t)NN * FW];
__device__ float    g_xr[(size_t)NN * FW];
__device__ float    g_h [(size_t)NN * FW];
__device__ float    g_agg[(size_t)NN * FW];
__device__ float    g_logits[(size_t)EP * 4];
__device__ unsigned g_maxb[NN * 4];
__device__ float    g_denom[NN * 4];
__device__ float    g_ewsum;

// monotonic float <-> unsigned mapping for atomicMax on floats
__device__ __forceinline__ unsigned fmono(float x) {
    unsigned u = __float_as_uint(x);
    return (u & 0x80000000u) ? ~u : (u | 0x80000000u);
}
__device__ __forceinline__ float fmono_dec(unsigned u) {
    return __uint_as_float((u & 0x80000000u) ? (u ^ 0x80000000u) : ~u);
}
#define MONO_NEG_INF 0x007FFFFFu   // fmono(-inf)

// ---------------- edge-weight mean -------------------------------------------
__global__ void k_zero_scalar() { g_ewsum = 0.f; }

__global__ void k_ew_reduce(const float* __restrict__ ew) {
    float s = 0.f;
    int stride = gridDim.x * blockDim.x;
    for (int i = blockIdx.x * blockDim.x + threadIdx.x; i < NE; i += stride)
        s += ew[i];
    #pragma unroll
    for (int o = 16; o; o >>= 1) s += __shfl_xor_sync(0xffffffffu, s, o);
    __shared__ float sm[8];
    int w = threadIdx.x >> 5, l = threadIdx.x & 31;
    if (l == 0) sm[w] = s;
    __syncthreads();
    if (threadIdx.x < 8) {
        s = sm[threadIdx.x];
        #pragma unroll
        for (int o = 4; o; o >>= 1) s += __shfl_xor_sync(0x000000ffu, s, o, 8);
        if (threadIdx.x == 0) atomicAdd(&g_ewsum, s);
    }
}

// ---------------- GEMM: C[M,128] = A[M,128] @ W[128,128] ---------------------
// warp handles 8 rows x 128 cols; all float4 traffic; FFMA-bound.
__global__ void k_gemm128(const float* __restrict__ Aext, int asel,
                          const float* __restrict__ W, int csel) {
    const float* __restrict__ A = asel ? g_h : Aext;
    float* __restrict__ C = csel ? g_xr : g_xl;
    int warp = (blockIdx.x * blockDim.x + threadIdx.x) >> 5;
    int lane = threadIdx.x & 31;
    if (warp >= NN / 8) return;
    size_t r0 = (size_t)warp * 8;

    float4 acc[8];
    #pragma unroll
    for (int i = 0; i < 8; i++) acc[i] = make_float4(0.f, 0.f, 0.f, 0.f);

    const float4* __restrict__ W4 = (const float4*)W;
    #pragma unroll 4
    for (int k = 0; k < 128; k += 4) {
        float4 w0 = W4[(k + 0) * 32 + lane];
        float4 w1 = W4[(k + 1) * 32 + lane];
        float4 w2 = W4[(k + 2) * 32 + lane];
        float4 w3 = W4[(k + 3) * 32 + lane];
        #pragma unroll
        for (int i = 0; i < 8; i++) {
            float4 a = *(const float4*)&A[(r0 + i) * 128 + k];
            acc[i].x += a.x * w0.x + a.y * w1.x + a.z * w2.x + a.w * w3.x;
            acc[i].y += a.x * w0.y + a.y * w1.y + a.z * w2.y + a.w * w3.y;
            acc[i].z += a.x * w0.z + a.y * w1.z + a.z * w2.z + a.w * w3.z;
            acc[i].w += a.x * w0.w + a.y * w1.w + a.z * w2.w + a.w * w3.w;
        }
    }
    #pragma unroll
    for (int i = 0; i < 8; i++)
        *(float4*)&C[(r0 + i) * 128 + lane * 4] = acc[i];
}

// ---------------- per-layer init ---------------------------------------------
__global__ void k_init() {
    int i = blockIdx.x * blockDim.x + threadIdx.x;
    if (i < NN * FW) g_agg[i] = 0.f;
    if (i < NN * 4) { g_maxb[i] = MONO_NEG_INF; g_denom[i] = 0.f; }
}

// ---------------- logits + segment max (warp per edge) -----------------------
__global__ void k_logits(const int* __restrict__ esrc, const int* __restrict__ edst,
                         const float* __restrict__ ew,
                         const float* __restrict__ We, const float* __restrict__ att) {
    int e = (blockIdx.x * blockDim.x + threadIdx.x) >> 5;
    if (e >= EP) return;
    int lane = threadIdx.x & 31;
    int s, d; float w;
    if (e < NE) { s = esrc[e]; d = edst[e]; w = ew[e]; }
    else        { s = d = e - NE; w = g_ewsum * (1.0f / NE); }

    float4 a  = *(const float4*)&g_xl[(size_t)s * 128 + lane * 4];
    float4 b  = *(const float4*)&g_xr[(size_t)d * 128 + lane * 4];
    float4 we = *(const float4*)&We[lane * 4];
    float4 at = *(const float4*)&att[lane * 4];

    float z0 = a.x + b.x + w * we.x; z0 = z0 > 0.f ? z0 : 0.2f * z0;
    float z1 = a.y + b.y + w * we.y; z1 = z1 > 0.f ? z1 : 0.2f * z1;
    float z2 = a.z + b.z + w * we.z; z2 = z2 > 0.f ? z2 : 0.2f * z2;
    float z3 = a.w + b.w + w * we.w; z3 = z3 > 0.f ? z3 : 0.2f * z3;

    float p = z0 * at.x + z1 * at.y + z2 * at.z + z3 * at.w;
    p += __shfl_xor_sync(0xffffffffu, p, 1);
    p += __shfl_xor_sync(0xffffffffu, p, 2);
    p += __shfl_xor_sync(0xffffffffu, p, 4);

    if ((lane & 7) == 0) {
        int h = lane >> 3;
        g_logits[(size_t)e * 4 + h] = p;
        atomicMax(&g_maxb[d * 4 + h], fmono(p));
    }
}

// ---------------- exp + segment sum (thread per edge*head) -------------------
__global__ void k_exp(const int* __restrict__ edst) {
    int idx = blockIdx.x * blockDim.x + threadIdx.x;
    if (idx >= EP * 4) return;
    int e = idx >> 2, hh = idx & 3;
    int d = (e < NE) ? edst[e] : (e - NE);
    float m = fmono_dec(g_maxb[d * 4 + hh]);
    float p = __expf(g_logits[idx] - m);
    g_logits[idx] = p;
    atomicAdd(&g_denom[d * 4 + hh], p);
}

// ---------------- weighted aggregation (warp per edge) -----------------------
__global__ void k_agg(const int* __restrict__ esrc, const int* __restrict__ edst) {
    int e = (blockIdx.x * blockDim.x + threadIdx.x) >> 5;
    if (e >= EP) return;
    int lane = threadIdx.x & 31;
    int s, d;
    if (e < NE) { s = esrc[e]; d = edst[e]; }
    else        { s = d = e - NE; }
    int h = lane >> 3;
    float alpha = g_logits[(size_t)e * 4 + h] / (g_denom[d * 4 + h] + 1e-16f);
    float4 a = *(const float4*)&g_xl[(size_t)s * 128 + lane * 4];
    float* dst = &g_agg[(size_t)d * 128 + lane * 4];
    asm volatile("red.global.add.v4.f32 [%0], {%1,%2,%3,%4};"
                 :: "l"(dst), "f"(a.x * alpha), "f"(a.y * alpha),
                    "f"(a.z * alpha), "f"(a.w * alpha) : "memory");
}

// ---------------- layer-1 epilogue: bias + ELU -> g_h ------------------------
__global__ void k_elu(const float* __restrict__ b1) {
    int idx = blockIdx.x * blockDim.x + threadIdx.x;
    if (idx >= NN * FW) return;
    float v = g_agg[idx] + b1[idx & 127];
    g_h[idx] = v > 0.f ? v : (__expf(v) - 1.f);
}

// ---------------- layer-2 epilogue: mean over heads + bias -> out ------------
__global__ void k_final(const float* __restrict__ b2, float* __restrict__ out) {
    int idx = blockIdx.x * blockDim.x + threadIdx.x;
    if (idx >= NN * 32) return;
    int n = idx >> 5, c = idx & 31;
    size_t base = (size_t)n * 128 + c;
    float v = 0.25f * (g_agg[base] + g_agg[base + 32] + g_agg[base + 64] + g_agg[base + 96]);
    out[idx] = v + b2[c];
}

// ---------------- launch ------------------------------------------------------
extern "C" void kernel_launch(void* const* d_in, const int* in_sizes, int n_in,
                              void* d_out, int out_size) {
    const float* x    = (const float*)d_in[0];
    const int*   ei   = (const int*)  d_in[1];
    const float* ew   = (const float*)d_in[2];
    const float* Wl1  = (const float*)d_in[3];
    const float* Wr1  = (const float*)d_in[4];
    const float* We1  = (const float*)d_in[5];
    const float* att1 = (const float*)d_in[6];
    const float* b1   = (const float*)d_in[7];
    const float* Wl2  = (const float*)d_in[8];
    const float* Wr2  = (const float*)d_in[9];
    const float* We2  = (const float*)d_in[10];
    const float* att2 = (const float*)d_in[11];
    const float* b2   = (const float*)d_in[12];
    float* out = (float*)d_out;

    const int* esrc = ei;
    const int* edst = ei + NE;

    const int GEMM_BLK = (NN / 8 * 32 + 255) / 256;     // 782
    const int INIT_BLK = (NN * FW + 255) / 256;         // 25000
    const int EDGE_BLK = EP / 8;                        // 206250 (warp/edge, 8 warps/blk)
    const int EXP_BLK  = (EP * 4 + 255) / 256;          // 25782
    const int FIN_BLK  = (NN * 32 + 255) / 256;         // 6250

    k_zero_scalar<<<1, 1>>>();
    k_ew_reduce<<<448, 256>>>(ew);

    // ---- layer 1 ----
    k_gemm128<<<GEMM_BLK, 256>>>(x, 0, Wl1, 0);
    k_gemm128<<<GEMM_BLK, 256>>>(x, 0, Wr1, 1);
    k_init<<<INIT_BLK, 256>>>();
    k_logits<<<EDGE_BLK, 256>>>(esrc, edst, ew, We1, att1);
    k_exp<<<EXP_BLK, 256>>>(edst);
    k_agg<<<EDGE_BLK, 256>>>(esrc, edst);
    k_elu<<<INIT_BLK, 256>>>(b1);

    // ---- layer 2 ----
    k_gemm128<<<GEMM_BLK, 256>>>(x, 1, Wl2, 0);
    k_gemm128<<<GEMM_BLK, 256>>>(x, 1, Wr2, 1);
    k_init<<<INIT_BLK, 256>>>();
    k_logits<<<EDGE_BLK, 256>>>(esrc, edst, ew, We2, att2);
    k_exp<<<EXP_BLK, 256>>>(edst);
    k_agg<<<EDGE_BLK, 256>>>(esrc, edst);
    k_final<<<FIN_BLK, 256>>>(b2, out);
}

// round 4
// speedup vs baseline: 1.6355x; 1.6355x over previous
#include <cuda_runtime.h>
#include <cuda_bf16.h>

#define NN 50000
#define NE 1600000
#define EP 1650000     // NE + NN self loops
#define FW 128         // H*C feature width

// ---------------- scratch (device globals; no allocation allowed) ------------
__device__ float g_xl[(size_t)NN * FW];
__device__ float g_xr[(size_t)NN * FW];
__device__ float g_h [(size_t)NN * FW];
__device__ float g_agg[(size_t)NN * FW];
__device__ float g_denom[NN * 4];          // sum of exp(logit); inverted in-place
__device__ float g_ewsum;

// ---------------- edge-weight mean -------------------------------------------
__global__ void k_zero_scalar() { g_ewsum = 0.f; }

__global__ void k_ew_reduce(const float* __restrict__ ew) {
    float s = 0.f;
    int stride = gridDim.x * blockDim.x;
    for (int i = blockIdx.x * blockDim.x + threadIdx.x; i < NE; i += stride)
        s += ew[i];
    #pragma unroll
    for (int o = 16; o; o >>= 1) s += __shfl_xor_sync(0xffffffffu, s, o);
    __shared__ float sm[8];
    int w = threadIdx.x >> 5, l = threadIdx.x & 31;
    if (l == 0) sm[w] = s;
    __syncthreads();
    if (threadIdx.x < 8) {
        s = sm[threadIdx.x];
        #pragma unroll
        for (int o = 4; o; o >>= 1) s += __shfl_xor_sync(0x000000ffu, s, o, 8);
        if (threadIdx.x == 0) atomicAdd(&g_ewsum, s);
    }
}

// ---------------- GEMM: C[M,128] = A[M,128] @ W[128,128] ---------------------
// warp handles 8 rows x 128 cols; all float4 traffic; FFMA-bound (~86% of
// FFMA-3reg rt=2 floor already).
__global__ void k_gemm128(const float* __restrict__ Aext, int asel,
                          const float* __restrict__ W, int csel) {
    const float* __restrict__ A = asel ? g_h : Aext;
    float* __restrict__ C = csel ? g_xr : g_xl;
    int warp = (blockIdx.x * blockDim.x + threadIdx.x) >> 5;
    int lane = threadIdx.x & 31;
    if (warp >= NN / 8) return;
    size_t r0 = (size_t)warp * 8;

    float4 acc[8];
    #pragma unroll
    for (int i = 0; i < 8; i++) acc[i] = make_float4(0.f, 0.f, 0.f, 0.f);

    const float4* __restrict__ W4 = (const float4*)W;
    #pragma unroll 4
    for (int k = 0; k < 128; k += 4) {
        float4 w0 = W4[(k + 0) * 32 + lane];
        float4 w1 = W4[(k + 1) * 32 + lane];
        float4 w2 = W4[(k + 2) * 32 + lane];
        float4 w3 = W4[(k + 3) * 32 + lane];
        #pragma unroll
        for (int i = 0; i < 8; i++) {
            float4 a = *(const float4*)&A[(r0 + i) * 128 + k];
            acc[i].x += a.x * w0.x + a.y * w1.x + a.z * w2.x + a.w * w3.x;
            acc[i].y += a.x * w0.y + a.y * w1.y + a.z * w2.y + a.w * w3.y;
            acc[i].z += a.x * w0.z + a.y * w1.z + a.z * w2.z + a.w * w3.z;
            acc[i].w += a.x * w0.w + a.y * w1.w + a.z * w2.w + a.w * w3.w;
        }
    }
    #pragma unroll
    for (int i = 0; i < 8; i++)
        *(float4*)&C[(r0 + i) * 128 + lane * 4] = acc[i];
}

// ---------------- per-layer init (zero agg + denom) ---------------------------
__global__ void k_init() {
    int i = blockIdx.x * blockDim.x + threadIdx.x;
    if (i < NN * FW / 4) ((float4*)g_agg)[i] = make_float4(0.f, 0.f, 0.f, 0.f);
    if (i < NN * 4) g_denom[i] = 0.f;
}

// ---------------- SINGLE fused edge pass (warp per edge) ---------------------
// logit -> p=exp(logit) -> denom += p ; agg += p * xl[src]  (unnormalized).
// Normalization agg *= 1/denom happens in the per-node epilogue, since denom
// is constant per (dst, head): sum_e (p_e/denom) xl = (sum_e p_e xl)/denom.
// Raw exp is safe: logits are O(10) << 88 overflow limit.
__global__ void k_edge(const int* __restrict__ esrc, const int* __restrict__ edst,
                       const float* __restrict__ ew,
                       const float* __restrict__ We, const float* __restrict__ att) {
    int e = (blockIdx.x * blockDim.x + threadIdx.x) >> 5;
    if (e >= EP) return;
    int lane = threadIdx.x & 31;
    int s, d; float w;
    if (e < NE) { s = esrc[e]; d = edst[e]; w = ew[e]; }
    else        { s = d = e - NE; w = g_ewsum * (1.0f / NE); }

    float4 a  = *(const float4*)&g_xl[(size_t)s * 128 + lane * 4];
    float4 b  = *(const float4*)&g_xr[(size_t)d * 128 + lane * 4];
    float4 we = *(const float4*)&We[lane * 4];
    float4 at = *(const float4*)&att[lane * 4];

    float z0 = a.x + b.x + w * we.x; z0 = z0 > 0.f ? z0 : 0.2f * z0;
    float z1 = a.y + b.y + w * we.y; z1 = z1 > 0.f ? z1 : 0.2f * z1;
    float z2 = a.z + b.z + w * we.z; z2 = z2 > 0.f ? z2 : 0.2f * z2;
    float z3 = a.w + b.w + w * we.w; z3 = z3 > 0.f ? z3 : 0.2f * z3;

    float p = z0 * at.x + z1 * at.y + z2 * at.z + z3 * at.w;
    // butterfly over the 8-lane head group: afterwards ALL 8 lanes hold the sum
    p += __shfl_xor_sync(0xffffffffu, p, 1);
    p += __shfl_xor_sync(0xffffffffu, p, 2);
    p += __shfl_xor_sync(0xffffffffu, p, 4);

    float pe = __expf(p);
    if ((lane & 7) == 0)
        atomicAdd(&g_denom[d * 4 + (lane >> 3)], pe);

    float* dst = &g_agg[(size_t)d * 128 + lane * 4];
    asm volatile("red.global.add.v4.f32 [%0], {%1,%2,%3,%4};"
                 :: "l"(dst), "f"(a.x * pe), "f"(a.y * pe),
                    "f"(a.z * pe), "f"(a.w * pe) : "memory");
}

// ---------------- denom -> reciprocal ----------------------------------------
__global__ void k_inv() {
    int i = blockIdx.x * blockDim.x + threadIdx.x;
    if (i < NN * 4) g_denom[i] = 1.0f / (g_denom[i] + 1e-16f);
}

// ---------------- layer-1 epilogue: normalize + bias + ELU -> g_h ------------
__global__ void k_elu(const float* __restrict__ b1) {
    int idx = blockIdx.x * blockDim.x + threadIdx.x;
    if (idx >= NN * FW) return;
    int n = idx >> 7, h = (idx >> 5) & 3;
    float v = g_agg[idx] * g_denom[n * 4 + h] + b1[idx & 127];
    g_h[idx] = v > 0.f ? v : (__expf(v) - 1.f);
}

// ---------------- layer-2 epilogue: normalize + head-mean + bias -> out ------
__global__ void k_final(const float* __restrict__ b2, float* __restrict__ out) {
    int idx = blockIdx.x * blockDim.x + threadIdx.x;
    if (idx >= NN * 32) return;
    int n = idx >> 5, c = idx & 31;
    size_t base = (size_t)n * 128 + c;
    const float* inv = &g_denom[n * 4];
    float v = 0.25f * (g_agg[base]      * inv[0] + g_agg[base + 32] * inv[1] +
                       g_agg[base + 64] * inv[2] + g_agg[base + 96] * inv[3]);
    out[idx] = v + b2[c];
}

// ---------------- launch ------------------------------------------------------
extern "C" void kernel_launch(void* const* d_in, const int* in_sizes, int n_in,
                              void* d_out, int out_size) {
    const float* x    = (const float*)d_in[0];
    const int*   ei   = (const int*)  d_in[1];
    const float* ew   = (const float*)d_in[2];
    const float* Wl1  = (const float*)d_in[3];
    const float* Wr1  = (const float*)d_in[4];
    const float* We1  = (const float*)d_in[5];
    const float* att1 = (const float*)d_in[6];
    const float* b1   = (const float*)d_in[7];
    const float* Wl2  = (const float*)d_in[8];
    const float* Wr2  = (const float*)d_in[9];
    const float* We2  = (const float*)d_in[10];
    const float* att2 = (const float*)d_in[11];
    const float* b2   = (const float*)d_in[12];
    float* out = (float*)d_out;

    const int* esrc = ei;
    const int* edst = ei + NE;

    const int GEMM_BLK = (NN / 8 * 32 + 255) / 256;     // 782
    const int INIT_BLK = (NN * FW / 4 + 255) / 256;     // 6250
    const int EW_BLK   = (NN * FW + 255) / 256;         // 25000
    const int EDGE_BLK = EP / 8;                        // 206250 (warp/edge, 8 warps/blk)
    const int INV_BLK  = (NN * 4 + 255) / 256;          // 782
    const int FIN_BLK  = (NN * 32 + 255) / 256;         // 6250

    k_zero_scalar<<<1, 1>>>();
    k_ew_reduce<<<448, 256>>>(ew);

    // ---- layer 1 ----
    k_gemm128<<<GEMM_BLK, 256>>>(x, 0, Wl1, 0);
    k_gemm128<<<GEMM_BLK, 256>>>(x, 0, Wr1, 1);
    k_init<<<INIT_BLK, 256>>>();
    k_edge<<<EDGE_BLK, 256>>>(esrc, edst, ew, We1, att1);
    k_inv<<<INV_BLK, 256>>>();
    k_elu<<<EW_BLK, 256>>>(b1);

    // ---- layer 2 ----
    k_gemm128<<<GEMM_BLK, 256>>>(x, 1, Wl2, 0);
    k_gemm128<<<GEMM_BLK, 256>>>(x, 1, Wr2, 1);
    k_init<<<INIT_BLK, 256>>>();
    k_edge<<<EDGE_BLK, 256>>>(esrc, edst, ew, We2, att2);
    k_inv<<<INV_BLK, 256>>>();
    k_final<<<FIN_BLK, 256>>>(b2, out);
}

// round 5
// speedup vs baseline: 1.6864x; 1.0311x over previous
#include <cuda_runtime.h>
#include <cuda_bf16.h>
#include <cstdint>

#define NN 50000
#define NE 1600000
#define EP 1650000     // NE + NN self loops
#define FW 128         // H*C feature width
#define GS 136         // smem stride (floats): banks = 8*tig + g, conflict-free

// ---------------- scratch (device globals; no allocation allowed) ------------
__device__ float g_xl[(size_t)NN * FW];
__device__ float g_xr[(size_t)NN * FW];
__device__ float g_h [(size_t)NN * FW];
__device__ float g_agg[(size_t)NN * FW];
__device__ float g_denom[NN * 4];          // sum of exp(logit); inverted in-place
__device__ float g_ewsum;

// ---------------- edge-weight mean -------------------------------------------
__global__ void k_zero_scalar() { g_ewsum = 0.f; }

__global__ void k_ew_reduce(const float* __restrict__ ew) {
    float s = 0.f;
    int stride = gridDim.x * blockDim.x;
    for (int i = blockIdx.x * blockDim.x + threadIdx.x; i < NE; i += stride)
        s += ew[i];
    #pragma unroll
    for (int o = 16; o; o >>= 1) s += __shfl_xor_sync(0xffffffffu, s, o);
    __shared__ float sm[8];
    int w = threadIdx.x >> 5, l = threadIdx.x & 31;
    if (l == 0) sm[w] = s;
    __syncthreads();
    if (threadIdx.x < 8) {
        s = sm[threadIdx.x];
        #pragma unroll
        for (int o = 4; o; o >>= 1) s += __shfl_xor_sync(0x000000ffu, s, o, 8);
        if (threadIdx.x == 0) atomicAdd(&g_ewsum, s);
    }
}

// ---------------- tf32 helpers ------------------------------------------------
__device__ __forceinline__ void tf32split(float x, uint32_t& hi, uint32_t& lo) {
    uint32_t h;
    asm("cvt.rna.tf32.f32 %0, %1;" : "=r"(h) : "f"(x));
    float r = x - __uint_as_float(h);
    uint32_t l;
    asm("cvt.rna.tf32.f32 %0, %1;" : "=r"(l) : "f"(r));
    hi = h; lo = l;
}

#define MMA_TF32(ACC, A0, A1, A2, A3, B0, B1)                                   \
    asm volatile("mma.sync.aligned.m16n8k8.row.col.f32.tf32.tf32.f32 "          \
                 "{%0,%1,%2,%3},{%4,%5,%6,%7},{%8,%9},{%0,%1,%2,%3};"           \
                 : "+f"(ACC[0]), "+f"(ACC[1]), "+f"(ACC[2]), "+f"(ACC[3])       \
                 : "r"(A0), "r"(A1), "r"(A2), "r"(A3), "r"(B0), "r"(B1))

// ---------------- tensor-core GEMM: C[M,128] = A[M,128] @ W[128,128] ---------
// 3xTF32: a=ah+al, b=bh+bl; keep ah*bh + ah*bl + al*bh (err ~2^-22).
// Block: 256 thr = 8 warps; warp does 16 rows x 128 cols (16 n-tiles of 8).
// W split hi/lo staged in smem (stride GS=136 -> conflict-free B LDS).
__global__ void __launch_bounds__(256, 1) k_gemm_tc(
        const float* __restrict__ Aext, int asel,
        const float* __restrict__ W, int csel) {
    const float* __restrict__ A = asel ? g_h : Aext;
    float* __restrict__ C = csel ? g_xr : g_xl;

    extern __shared__ float sw[];          // [2][128][GS]
    float* whi = sw;
    float* wlo = sw + 128 * GS;

    int tid = threadIdx.x;
    for (int i = tid; i < 128 * 128; i += 256) {
        int k = i >> 7, n = i & 127;
        uint32_t h, l;
        tf32split(W[i], h, l);
        whi[k * GS + n] = __uint_as_float(h);
        wlo[k * GS + n] = __uint_as_float(l);
    }
    __syncthreads();

    int warp = tid >> 5, lane = tid & 31;
    int g = lane >> 2, tig = lane & 3;
    int r0 = (blockIdx.x * 8 + warp) * 16;
    if (r0 >= NN) return;                  // NN % 16 == 0: no partial warps

    const float* arow0 = A + (size_t)(r0 + g) * 128;
    const float* arow1 = A + (size_t)(r0 + g + 8) * 128;

    float acc[16][4];
    #pragma unroll
    for (int n = 0; n < 16; n++)
        #pragma unroll
        for (int j = 0; j < 4; j++) acc[n][j] = 0.f;

    #pragma unroll 4
    for (int ks = 0; ks < 16; ks++) {
        int k0 = ks * 8;
        uint32_t ah[4], al[4];
        tf32split(arow0[k0 + tig],     ah[0], al[0]);
        tf32split(arow1[k0 + tig],     ah[1], al[1]);
        tf32split(arow0[k0 + tig + 4], ah[2], al[2]);
        tf32split(arow1[k0 + tig + 4], ah[3], al[3]);

        const float* wh0 = &whi[(k0 + tig) * GS + g];
        const float* wh1 = &whi[(k0 + tig + 4) * GS + g];
        const float* wl0 = &wlo[(k0 + tig) * GS + g];
        const float* wl1 = &wlo[(k0 + tig + 4) * GS + g];

        #pragma unroll
        for (int n = 0; n < 16; n++) {
            uint32_t bh0 = __float_as_uint(wh0[n * 8]);
            uint32_t bh1 = __float_as_uint(wh1[n * 8]);
            uint32_t bl0 = __float_as_uint(wl0[n * 8]);
            uint32_t bl1 = __float_as_uint(wl1[n * 8]);
            MMA_TF32(acc[n], ah[0], ah[1], ah[2], ah[3], bh0, bh1);
            MMA_TF32(acc[n], ah[0], ah[1], ah[2], ah[3], bl0, bl1);
            MMA_TF32(acc[n], al[0], al[1], al[2], al[3], bh0, bh1);
        }
    }

    float* c0 = C + (size_t)(r0 + g) * 128 + 2 * tig;
    float* c1 = C + (size_t)(r0 + g + 8) * 128 + 2 * tig;
    #pragma unroll
    for (int n = 0; n < 16; n++) {
        *(float2*)&c0[n * 8] = make_float2(acc[n][0], acc[n][1]);
        *(float2*)&c1[n * 8] = make_float2(acc[n][2], acc[n][3]);
    }
}

// ---------------- per-layer init (zero agg + denom) ---------------------------
__global__ void k_init() {
    int i = blockIdx.x * blockDim.x + threadIdx.x;
    if (i < NN * FW / 4) ((float4*)g_agg)[i] = make_float4(0.f, 0.f, 0.f, 0.f);
    if (i < NN * 4) g_denom[i] = 0.f;
}

// ---------------- SINGLE fused edge pass (warp per edge) ---------------------
// logit -> p=exp(logit) -> denom += p ; agg += p * xl[src]  (unnormalized).
// Normalization happens in the per-node epilogue (denom const per dst,head).
__global__ void k_edge(const int* __restrict__ esrc, const int* __restrict__ edst,
                       const float* __restrict__ ew,
                       const float* __restrict__ We, const float* __restrict__ att) {
    int e = (blockIdx.x * blockDim.x + threadIdx.x) >> 5;
    if (e >= EP) return;
    int lane = threadIdx.x & 31;
    int s, d; float w;
    if (e < NE) { s = esrc[e]; d = edst[e]; w = ew[e]; }
    else        { s = d = e - NE; w = g_ewsum * (1.0f / NE); }

    float4 a  = *(const float4*)&g_xl[(size_t)s * 128 + lane * 4];
    float4 b  = *(const float4*)&g_xr[(size_t)d * 128 + lane * 4];
    float4 we = *(const float4*)&We[lane * 4];
    float4 at = *(const float4*)&att[lane * 4];

    float z0 = a.x + b.x + w * we.x; z0 = z0 > 0.f ? z0 : 0.2f * z0;
    float z1 = a.y + b.y + w * we.y; z1 = z1 > 0.f ? z1 : 0.2f * z1;
    float z2 = a.z + b.z + w * we.z; z2 = z2 > 0.f ? z2 : 0.2f * z2;
    float z3 = a.w + b.w + w * we.w; z3 = z3 > 0.f ? z3 : 0.2f * z3;

    float p = z0 * at.x + z1 * at.y + z2 * at.z + z3 * at.w;
    p += __shfl_xor_sync(0xffffffffu, p, 1);
    p += __shfl_xor_sync(0xffffffffu, p, 2);
    p += __shfl_xor_sync(0xffffffffu, p, 4);

    float pe = __expf(p);
    if ((lane & 7) == 0)
        atomicAdd(&g_denom[d * 4 + (lane >> 3)], pe);

    float* dst = &g_agg[(size_t)d * 128 + lane * 4];
    asm volatile("red.global.add.v4.f32 [%0], {%1,%2,%3,%4};"
                 :: "l"(dst), "f"(a.x * pe), "f"(a.y * pe),
                    "f"(a.z * pe), "f"(a.w * pe) : "memory");
}

// ---------------- denom -> reciprocal ----------------------------------------
__global__ void k_inv() {
    int i = blockIdx.x * blockDim.x + threadIdx.x;
    if (i < NN * 4) g_denom[i] = 1.0f / (g_denom[i] + 1e-16f);
}

// ---------------- layer-1 epilogue: normalize + bias + ELU -> g_h ------------
__global__ void k_elu(const float* __restrict__ b1) {
    int idx = blockIdx.x * blockDim.x + threadIdx.x;
    if (idx >= NN * FW) return;
    int n = idx >> 7, h = (idx >> 5) & 3;
    float v = g_agg[idx] * g_denom[n * 4 + h] + b1[idx & 127];
    g_h[idx] = v > 0.f ? v : (__expf(v) - 1.f);
}

// ---------------- layer-2 epilogue: normalize + head-mean + bias -> out ------
__global__ void k_final(const float* __restrict__ b2, float* __restrict__ out) {
    int idx = blockIdx.x * blockDim.x + threadIdx.x;
    if (idx >= NN * 32) return;
    int n = idx >> 5, c = idx & 31;
    size_t base = (size_t)n * 128 + c;
    const float* inv = &g_denom[n * 4];
    float v = 0.25f * (g_agg[base]      * inv[0] + g_agg[base + 32] * inv[1] +
                       g_agg[base + 64] * inv[2] + g_agg[base + 96] * inv[3]);
    out[idx] = v + b2[c];
}

// ---------------- launch ------------------------------------------------------
extern "C" void kernel_launch(void* const* d_in, const int* in_sizes, int n_in,
                              void* d_out, int out_size) {
    const float* x    = (const float*)d_in[0];
    const int*   ei   = (const int*)  d_in[1];
    const float* ew   = (const float*)d_in[2];
    const float* Wl1  = (const float*)d_in[3];
    const float* Wr1  = (const float*)d_in[4];
    const float* We1  = (const float*)d_in[5];
    const float* att1 = (const float*)d_in[6];
    const float* b1   = (const float*)d_in[7];
    const float* Wl2  = (const float*)d_in[8];
    const float* Wr2  = (const float*)d_in[9];
    const float* We2  = (const float*)d_in[10];
    const float* att2 = (const float*)d_in[11];
    const float* b2   = (const float*)d_in[12];
    float* out = (float*)d_out;

    const int* esrc = ei;
    const int* edst = ei + NE;

    const int SMEM_W  = 2 * 128 * GS * 4;               // 139,264 B
    cudaFuncSetAttribute(k_gemm_tc,
                         cudaFuncAttributeMaxDynamicSharedMemorySize, SMEM_W);

    const int TC_BLK   = (NN + 127) / 128;              // 391
    const int INIT_BLK = (NN * FW / 4 + 255) / 256;     // 6250
    const int EW_BLK   = (NN * FW + 255) / 256;         // 25000
    const int EDGE_BLK = EP / 8;                        // 206250 (warp/edge)
    const int INV_BLK  = (NN * 4 + 255) / 256;          // 782
    const int FIN_BLK  = (NN * 32 + 255) / 256;         // 6250

    k_zero_scalar<<<1, 1>>>();
    k_ew_reduce<<<448, 256>>>(ew);

    // ---- layer 1 ----
    k_gemm_tc<<<TC_BLK, 256, SMEM_W>>>(x, 0, Wl1, 0);
    k_gemm_tc<<<TC_BLK, 256, SMEM_W>>>(x, 0, Wr1, 1);
    k_init<<<INIT_BLK, 256>>>();
    k_edge<<<EDGE_BLK, 256>>>(esrc, edst, ew, We1, att1);
    k_inv<<<INV_BLK, 256>>>();
    k_elu<<<EW_BLK, 256>>>(b1);

    // ---- layer 2 ----
    k_gemm_tc<<<TC_BLK, 256, SMEM_W>>>(x, 1, Wl2, 0);
    k_gemm_tc<<<TC_BLK, 256, SMEM_W>>>(x, 1, Wr2, 1);
    k_init<<<INIT_BLK, 256>>>();
    k_edge<<<EDGE_BLK, 256>>>(esrc, edst, ew, We2, att2);
    k_inv<<<INV_BLK, 256>>>();
    k_final<<<FIN_BLK, 256>>>(b2, out);
}